// round 4
// baseline (speedup 1.0000x reference)
#include <cuda_runtime.h>
#include <cstddef>

#define NB 32
#define TT 2048
#define DD 512
#define HH 512
#define GG 2048   // 4*HH

// ---------------- device scratch (no allocations allowed) ----------------
__device__ float g_P[(size_t)TT * GG * NB];   // [t][g][n]  precomputed x@W_ih^T + b_ih + b_hh
__device__ float g_h[2 * HH * NB];            // double-buffered hidden state, [k][n] layout
__device__ unsigned int g_bar;                // monotonic global barrier counter

// ---------------- f32x2 packed-FMA helpers (sm_100+ only) ----------------
__device__ __forceinline__ unsigned long long pk2(float lo, float hi) {
    unsigned long long r;
    asm("mov.b64 %0, {%1, %2};" : "=l"(r) : "f"(lo), "f"(hi));
    return r;
}
__device__ __forceinline__ void up2(unsigned long long v, float &lo, float &hi) {
    asm("mov.b64 {%0, %1}, %2;" : "=f"(lo), "=f"(hi) : "l"(v));
}
__device__ __forceinline__ void fma2(unsigned long long &d, unsigned long long a,
                                     unsigned long long b) {
    asm("fma.rn.f32x2 %0, %1, %2, %0;" : "+l"(d) : "l"(a), "l"(b));
}

// ---------------- reset kernel: zero h buffers + barrier counter ----------------
__global__ void reset_kernel() {
    int idx = blockIdx.x * blockDim.x + threadIdx.x;
    for (int i = idx; i < 2 * HH * NB; i += gridDim.x * blockDim.x) g_h[i] = 0.f;
    if (idx == 0) g_bar = 0u;
}

// ---------------- Phase 1: P[t][g][n] = sum_d W_ih[g][d]*x[n][t][d] + b_ih[g]+b_hh[g] ----
// Tile: 128 g-rows x 64 cols (2 timesteps x 32 batch), BK=16, 256 threads,
// microtile 8g x 4c per thread, f32x2 paired along g.
__global__ __launch_bounds__(256) void phase1_kernel(const float* __restrict__ x,
                                                     const float* __restrict__ Wih,
                                                     const float* __restrict__ bih,
                                                     const float* __restrict__ bhh) {
    __shared__ float Ws[16][132];   // [k][g-col], pad keeps 16B row alignment (132*4=528=33*16)
    __shared__ float Xs[16][68];    // [k][col],  pad 68*4=272=17*16

    const int tid = threadIdx.x;
    const int ct  = blockIdx.x;       // 0..1023 column tiles (2 t each)
    const int gt  = blockIdx.y;       // 0..15 gate-row tiles
    const int g0  = gt * 128;
    const int t0  = ct * 2;
    const int tx  = tid & 15;         // col group -> cols tx*4..tx*4+3
    const int ty  = tid >> 4;         // row group -> rows ty*8..ty*8+7
    const int gq  = tid >> 2;         // 0..63 (loader row / col index)
    const int kq  = tid & 3;          // 0..3  (loader k quad)

    unsigned long long acc[4][4];
    #pragma unroll
    for (int p = 0; p < 4; ++p)
        #pragma unroll
        for (int j = 0; j < 4; ++j) acc[p][j] = 0ULL;

    const int cc = gq;                 // load column 0..63
    const int lt = cc >> 5, nn = cc & 31;
    const float* xrow = x + ((size_t)nn * TT + (size_t)(t0 + lt)) * DD;

    for (int kt = 0; kt < 32; ++kt) {
        const int k0 = kt * 16;
        // load W tile (128 x 16)
        #pragma unroll
        for (int h = 0; h < 2; ++h) {
            int gcol = h * 64 + gq;
            float4 wv = *(const float4*)(Wih + (size_t)(g0 + gcol) * DD + k0 + kq * 4);
            Ws[kq * 4 + 0][gcol] = wv.x;
            Ws[kq * 4 + 1][gcol] = wv.y;
            Ws[kq * 4 + 2][gcol] = wv.z;
            Ws[kq * 4 + 3][gcol] = wv.w;
        }
        // load X tile (64 x 16)
        {
            float4 xv = *(const float4*)(xrow + k0 + kq * 4);
            Xs[kq * 4 + 0][cc] = xv.x;
            Xs[kq * 4 + 1][cc] = xv.y;
            Xs[kq * 4 + 2][cc] = xv.z;
            Xs[kq * 4 + 3][cc] = xv.w;
        }
        __syncthreads();
        #pragma unroll
        for (int k = 0; k < 16; ++k) {
            ulonglong2 wA = *(const ulonglong2*)&Ws[k][ty * 8];       // g pairs (0,1),(2,3)
            ulonglong2 wB = *(const ulonglong2*)&Ws[k][ty * 8 + 4];   // g pairs (4,5),(6,7)
            float4 xv = *(const float4*)&Xs[k][tx * 4];
            unsigned long long b0 = pk2(xv.x, xv.x);
            unsigned long long b1 = pk2(xv.y, xv.y);
            unsigned long long b2 = pk2(xv.z, xv.z);
            unsigned long long b3 = pk2(xv.w, xv.w);
            fma2(acc[0][0], wA.x, b0); fma2(acc[0][1], wA.x, b1);
            fma2(acc[0][2], wA.x, b2); fma2(acc[0][3], wA.x, b3);
            fma2(acc[1][0], wA.y, b0); fma2(acc[1][1], wA.y, b1);
            fma2(acc[1][2], wA.y, b2); fma2(acc[1][3], wA.y, b3);
            fma2(acc[2][0], wB.x, b0); fma2(acc[2][1], wB.x, b1);
            fma2(acc[2][2], wB.x, b2); fma2(acc[2][3], wB.x, b3);
            fma2(acc[3][0], wB.y, b0); fma2(acc[3][1], wB.y, b1);
            fma2(acc[3][2], wB.y, b2); fma2(acc[3][3], wB.y, b3);
        }
        __syncthreads();
    }

    // epilogue: add fused bias, store vectorized along n
    const int c0 = tx * 4;
    const int ltS = c0 >> 5, nS = c0 & 31;
    const int tS = t0 + ltS;
    #pragma unroll
    for (int p = 0; p < 4; ++p) {
        int gA = g0 + ty * 8 + 2 * p;
        float bA = bih[gA] + bhh[gA];
        float bB = bih[gA + 1] + bhh[gA + 1];
        float lo0, hi0, lo1, hi1, lo2_, hi2_, lo3, hi3;
        up2(acc[p][0], lo0, hi0);
        up2(acc[p][1], lo1, hi1);
        up2(acc[p][2], lo2_, hi2_);
        up2(acc[p][3], lo3, hi3);
        float* dst = g_P + (size_t)tS * (GG * NB) + (size_t)gA * NB + nS;
        float4 vA = make_float4(lo0 + bA, lo1 + bA, lo2_ + bA, lo3 + bA);
        float4 vB = make_float4(hi0 + bB, hi1 + bB, hi2_ + bB, hi3 + bB);
        *(float4*)dst = vA;
        *(float4*)(dst + NB) = vB;
    }
}

// ---------------- Phase 2: persistent sequential LSTM scan ----------------
// 128 blocks x 256 threads. Block b owns hidden units j0..j0+3 (all 4 gates),
// i.e. 16 gate rows. W_hh slice lives in shared (loaded once). Each warp
// covers k-chunk [warp*64, warp*64+64), lane = batch n. Cell state c lives
// in registers of threads 0..127 for the whole kernel.
__global__ __launch_bounds__(256, 1) void lstm_seq_kernel(const float* __restrict__ Whh,
                                                          float* __restrict__ y) {
    __shared__ float Wsh[HH * 16];        // [k][gi], gi = q*4+u  (32 KB)
    __shared__ float part[4][16][NB];     // k-split partials       (8 KB)

    const int tid  = threadIdx.x;
    const int warp = tid >> 5;
    const int lane = tid & 31;
    const int b    = blockIdx.x;          // 0..127
    const int j0   = b * 4;

    // load W_hh rows {q*512 + j0+u} into shared, k-major with gi fastest
    for (int i = tid; i < 16 * HH; i += 256) {
        int k  = i & (HH - 1);
        int gi = i >> 9;                   // 0..15
        int q  = gi >> 2, u = gi & 3;
        Wsh[k * 16 + gi] = Whh[(size_t)(q * HH + j0 + u) * HH + k];
    }

    const int u = warp;                    // gate-apply mapping for tid<128: (u, n=lane)
    float c_state = 0.f;
    __syncthreads();

    const int k0 = warp * 64;

    #pragma unroll 1
    for (int t = 0; t < TT; ++t) {
        const float* hin = g_h + (t & 1) * (HH * NB);
        float* hout      = g_h + ((t + 1) & 1) * (HH * NB);

        // prefetch this step's input projection (independent of h)
        float pre0 = 0.f, pre1 = 0.f, pre2 = 0.f, pre3 = 0.f;
        if (tid < 128) {
            const float* Pt = g_P + (size_t)t * (GG * NB) + (size_t)(j0 + u) * NB + lane;
            pre0 = Pt[0 * HH * NB];
            pre1 = Pt[1 * HH * NB];
            pre2 = Pt[2 * HH * NB];
            pre3 = Pt[3 * HH * NB];
        }

        // load h chunk into registers (L2-only: written by peer SMs last step)
        float hr[64];
        #pragma unroll
        for (int kk = 0; kk < 64; ++kk)
            hr[kk] = __ldcg(hin + (k0 + kk) * NB + lane);

        unsigned long long acc[8];
        #pragma unroll
        for (int p = 0; p < 8; ++p) acc[p] = 0ULL;

        #pragma unroll
        for (int kk = 0; kk < 64; ++kk) {
            unsigned long long hb = pk2(hr[kk], hr[kk]);
            const ulonglong2* wr = (const ulonglong2*)(Wsh + (size_t)(k0 + kk) * 16);
            ulonglong2 w03 = wr[0];   // gi 0..3
            ulonglong2 w47 = wr[1];   // gi 4..7
            ulonglong2 w8b = wr[2];   // gi 8..11
            ulonglong2 wcf = wr[3];   // gi 12..15
            fma2(acc[0], w03.x, hb); fma2(acc[1], w03.y, hb);
            fma2(acc[2], w47.x, hb); fma2(acc[3], w47.y, hb);
            fma2(acc[4], w8b.x, hb); fma2(acc[5], w8b.y, hb);
            fma2(acc[6], wcf.x, hb); fma2(acc[7], wcf.y, hb);
        }

        // combine 8 k-partials -> 4 (warps 0-3 store, warps 4-7 add)
        if (warp < 4) {
            #pragma unroll
            for (int p = 0; p < 8; ++p) {
                float lo, hi;
                up2(acc[p], lo, hi);
                part[warp][2 * p][lane]     = lo;
                part[warp][2 * p + 1][lane] = hi;
            }
        }
        __syncthreads();
        if (warp >= 4) {
            #pragma unroll
            for (int p = 0; p < 8; ++p) {
                float lo, hi;
                up2(acc[p], lo, hi);
                part[warp - 4][2 * p][lane]     += lo;
                part[warp - 4][2 * p + 1][lane] += hi;
            }
        }
        __syncthreads();

        // final reduce + gates (threads 0..127: one (hidden unit u, batch n) each)
        if (tid < 128) {
            float vi = pre0, vf = pre1, vo = pre2, vg = pre3;
            #pragma unroll
            for (int w = 0; w < 4; ++w) {
                vi += part[w][0 * 4 + u][lane];
                vf += part[w][1 * 4 + u][lane];
                vo += part[w][2 * 4 + u][lane];
                vg += part[w][3 * 4 + u][lane];
            }
            float ig = 1.f / (1.f + expf(-vi));
            float fg = 1.f / (1.f + expf(-vf));
            float og = 1.f / (1.f + expf(-vo));
            float gt = tanhf(vg);
            c_state = fg * c_state + ig * gt;
            float hn = og * tanhf(c_state);
            hout[(j0 + u) * NB + lane] = hn;
            y[(size_t)lane * (TT * HH) + (size_t)t * HH + (j0 + u)] = hn;
        }
        __syncthreads();   // hout writes + part reads complete before arrive / reuse

        // chip-wide barrier: monotonic counter (reset each launch by reset_kernel)
        if (tid == 0) {
            __threadfence();
            atomicAdd(&g_bar, 1u);
            unsigned tgt = (unsigned)(t + 1) * 128u;
            const volatile unsigned* vb = (const volatile unsigned*)&g_bar;
            while (*vb < tgt) { }
            __threadfence();
        }
        __syncthreads();
    }
}

// ---------------- launcher ----------------
extern "C" void kernel_launch(void* const* d_in, const int* in_sizes, int n_in,
                              void* d_out, int out_size) {
    const float* x   = (const float*)d_in[0];
    const float* Wih = (const float*)d_in[1];
    const float* bih = (const float*)d_in[2];
    const float* Whh = (const float*)d_in[3];
    const float* bhh = (const float*)d_in[4];
    float* y = (float*)d_out;

    reset_kernel<<<32, 256>>>();

    dim3 g1(1024, 16);
    phase1_kernel<<<g1, 256>>>(x, Wih, bih, bhh);

    lstm_seq_kernel<<<128, 256>>>(Whh, y);
}